// round 1
// baseline (speedup 1.0000x reference)
#include <cuda_runtime.h>

// Batched Newton-Schulz matrix sqrt: 1024 matrices of 128x128 fp32.
// One CTA per matrix; Y, Z, T live in shared memory (3 * 64KB = 192KB dynamic).
// 256 threads, each owns an 8x8 register tile of every 128x128 matmul.
//
// Algebraic savings vs reference's 15 matmuls:
//   iter 1: Z0 = I  =>  T1 = 1.5I - 0.5*Y0 (no matmul), Z1 = T1 (copy)  -> 1 mm
//   iters 2..4: full (3 mm each)
//   iter 5: Z5 never used -> skip T@Z                                    -> 2 mm
// Total: 12 matmuls per matrix.

#define NMAT 128
#define NT 256

__device__ __forceinline__ void mm128(const float* __restrict__ As,
                                      const float* __restrict__ Bs,
                                      float acc[64], int r0, int c0) {
#pragma unroll
    for (int i = 0; i < 64; i++) acc[i] = 0.0f;
#pragma unroll 4
    for (int k = 0; k < 128; k++) {
        float4 b0 = *(const float4*)(Bs + k * 128 + c0);
        float4 b1 = *(const float4*)(Bs + k * 128 + c0 + 4);
        float bb[8] = {b0.x, b0.y, b0.z, b0.w, b1.x, b1.y, b1.z, b1.w};
        float a[8];
#pragma unroll
        for (int i = 0; i < 8; i++) a[i] = As[(r0 + i) * 128 + k];
#pragma unroll
        for (int i = 0; i < 8; i++)
#pragma unroll
            for (int j = 0; j < 8; j++)
                acc[i * 8 + j] = fmaf(a[i], bb[j], acc[i * 8 + j]);
    }
}

__device__ __forceinline__ void store_plain(float* __restrict__ D,
                                            const float acc[64], int r0, int c0) {
#pragma unroll
    for (int i = 0; i < 8; i++) {
        *(float4*)(D + (r0 + i) * 128 + c0) =
            make_float4(acc[i * 8 + 0], acc[i * 8 + 1], acc[i * 8 + 2], acc[i * 8 + 3]);
        *(float4*)(D + (r0 + i) * 128 + c0 + 4) =
            make_float4(acc[i * 8 + 4], acc[i * 8 + 5], acc[i * 8 + 6], acc[i * 8 + 7]);
    }
}

// D = 1.5*I - 0.5*acc  (epilogue for the T update)
__device__ __forceinline__ void store_T(float* __restrict__ D,
                                        const float acc[64], int r0, int c0) {
#pragma unroll
    for (int i = 0; i < 8; i++) {
        float v[8];
#pragma unroll
        for (int j = 0; j < 8; j++) {
            v[j] = -0.5f * acc[i * 8 + j];
            if (r0 + i == c0 + j) v[j] += 1.5f;
        }
        *(float4*)(D + (r0 + i) * 128 + c0)     = make_float4(v[0], v[1], v[2], v[3]);
        *(float4*)(D + (r0 + i) * 128 + c0 + 4) = make_float4(v[4], v[5], v[6], v[7]);
    }
}

__global__ void __launch_bounds__(NT, 1)
ns_sqrt_kernel(const float* __restrict__ A, float* __restrict__ Out) {
    extern __shared__ float sm[];
    float* Y = sm;            // 16384 floats
    float* Z = sm + 16384;
    float* T = sm + 32768;
    __shared__ float red[8];

    const int b   = blockIdx.x;
    const int tid = threadIdx.x;
    const int ty = tid >> 4, tx = tid & 15;
    const int r0 = ty * 8, c0 = tx * 8;

    const float* Ab = A + (size_t)b * (NMAT * NMAT);
    float*       Ob = Out + (size_t)b * (NMAT * NMAT);

    // ---- Load A into Y (raw), accumulate Frobenius sum of squares ----
    float ss = 0.0f;
    const float4* A4 = (const float4*)Ab;
    float4* Y4 = (float4*)Y;
    for (int i = tid; i < 4096; i += NT) {
        float4 v = A4[i];
        Y4[i] = v;
        ss += v.x * v.x + v.y * v.y + v.z * v.z + v.w * v.w;
    }
#pragma unroll
    for (int o = 16; o; o >>= 1) ss += __shfl_xor_sync(0xffffffffu, ss, o);
    if ((tid & 31) == 0) red[tid >> 5] = ss;
    __syncthreads();
    float tot = 0.0f;
#pragma unroll
    for (int i = 0; i < 8; i++) tot += red[i];
    const float normA = sqrtf(tot);
    const float inv   = 1.0f / normA;

    // ---- Y = A/normA;  T1 = 1.5I - 0.5*Y;  Z1 = T1 ----
    for (int i = tid; i < 16384; i += NT) {
        float y = Y[i] * inv;
        Y[i] = y;
        int row = i >> 7, col = i & 127;
        float t = (row == col ? 1.5f : 0.0f) - 0.5f * y;
        T[i] = t;
        Z[i] = t;
    }
    __syncthreads();

    float acc[64];

    // ---- iter 1 (reduced): Y = Y @ T1 ----
    mm128(Y, T, acc, r0, c0);
    __syncthreads();
    store_plain(Y, acc, r0, c0);
    __syncthreads();

    // ---- iters 2..5 ----
#pragma unroll 1
    for (int it = 1; it < 5; ++it) {
        // T = 1.5I - 0.5 * (Z @ Y)
        mm128(Z, Y, acc, r0, c0);
        __syncthreads();
        store_T(T, acc, r0, c0);
        __syncthreads();

        // Y = Y @ T   (reads old Y; writeback after barrier)
        mm128(Y, T, acc, r0, c0);
        __syncthreads();
        store_plain(Y, acc, r0, c0);
        __syncthreads();

        if (it < 4) {
            // Z = T @ Z
            mm128(T, Z, acc, r0, c0);
            __syncthreads();
            store_plain(Z, acc, r0, c0);
            __syncthreads();
        }
    }

    // ---- Out = Y * sqrt(normA) ----
    const float s = sqrtf(normA);
    float4* O4 = (float4*)Ob;
    for (int i = tid; i < 4096; i += NT) {
        float4 v = Y4[i];
        v.x *= s; v.y *= s; v.z *= s; v.w *= s;
        O4[i] = v;
    }
}

extern "C" void kernel_launch(void* const* d_in, const int* in_sizes, int n_in,
                              void* d_out, int out_size) {
    const float* A = (const float*)d_in[0];
    float* out = (float*)d_out;
    const int nbatch = in_sizes[0] / (NMAT * NMAT);   // 32*32 = 1024
    const size_t smem = 3 * NMAT * NMAT * sizeof(float);  // 192 KB
    cudaFuncSetAttribute(ns_sqrt_kernel,
                         cudaFuncAttributeMaxDynamicSharedMemorySize, (int)smem);
    ns_sqrt_kernel<<<nbatch, NT, smem>>>(A, out);
}

// round 3
// speedup vs baseline: 2.4341x; 2.4341x over previous
#include <cuda_runtime.h>
#include <cuda_bf16.h>
#include <cstdint>

// Batched Newton-Schulz matrix sqrt: 1024 x (128x128 fp32), 5 iterations.
// Tensor-core path via warp-level mma.sync bf16 (valid on base sm_103 target;
// tcgen05 needs the sm_103a PTX target which this toolchain doesn't emit).
//
// fp32 emulated as bf16 hi+lo split: P@Q ~= Ph@Qh + Ph@Ql + Pl@Qh (fp32 acc).
// All iterates are symmetric (polynomials of SPD A0), so B-operand fragments
// (needing column access) are read from rows instead: Q[k][n] == Q[n][k].
//
// 12 logical matmuls per matrix:
//   iter1: Z0=I => T1 = 1.5I - 0.5*Y0 (free), Y1 = Y0@T1          (1 mm)
//   iters 2..4: T = 1.5I - 0.5*(Z@Y); Y = Y@T; Z = T@Z            (3 mm each)
//   iter5: Z unused afterwards -> skip T@Z                        (2 mm)

#define NMAT 128
#define NT 256
#define PITCH 136              // bf16 elems per smem row (272B -> conflict-free)
#define PITCH32 68             // u32 words per row

__device__ __forceinline__ void mma16816(float* d, const uint32_t* a,
                                         const uint32_t* b) {
    asm volatile(
        "mma.sync.aligned.m16n8k16.row.col.f32.bf16.bf16.f32 "
        "{%0,%1,%2,%3}, {%4,%5,%6,%7}, {%8,%9}, {%0,%1,%2,%3};"
        : "+f"(d[0]), "+f"(d[1]), "+f"(d[2]), "+f"(d[3])
        : "r"(a[0]), "r"(a[1]), "r"(a[2]), "r"(a[3]), "r"(b[0]), "r"(b[1]));
}

__device__ __forceinline__ uint32_t pack2(float v0, float v1) {
    __nv_bfloat16 h0 = __float2bfloat16(v0), h1 = __float2bfloat16(v1);
    return (uint32_t)__bfloat16_as_ushort(h0) |
           ((uint32_t)__bfloat16_as_ushort(h1) << 16);
}

// Split pair into hi / lo bf16x2 words.
__device__ __forceinline__ void split2(float v0, float v1, uint32_t& hw,
                                       uint32_t& lw) {
    __nv_bfloat16 h0 = __float2bfloat16(v0), h1 = __float2bfloat16(v1);
    float r0 = v0 - __bfloat162float(h0), r1 = v1 - __bfloat162float(h1);
    hw = (uint32_t)__bfloat16_as_ushort(h0) |
         ((uint32_t)__bfloat16_as_ushort(h1) << 16);
    lw = pack2(r0, r1);
}

// Fused 3-product matmul: acc += Ph@Qh + Ph@Ql + Pl@Qh over full K=128.
// Warp tile: rows [r0, r0+64), cols [c0, c0+32).
__device__ __forceinline__ void mm_full(const uint32_t* __restrict__ Ph,
                                        const uint32_t* __restrict__ Pl,
                                        const uint32_t* __restrict__ Qh,
                                        const uint32_t* __restrict__ Ql,
                                        float acc[4][4][4], int r0, int c0,
                                        int lane) {
    const int qr = lane >> 2;      // 0..7
    const int kp = lane & 3;       // k col-pair
#pragma unroll
    for (int k0 = 0; k0 < 8; k0++) {
        const int kw = k0 * 8 + kp;   // u32 word offset along K
        uint32_t ah[4][4], al[4][4], bh[4][2], bl[4][2];
#pragma unroll
        for (int mi = 0; mi < 4; mi++) {
            const int r = r0 + mi * 16 + qr;
            const int i0 = r * PITCH32 + kw;
            const int i1 = (r + 8) * PITCH32 + kw;
            ah[mi][0] = Ph[i0];     ah[mi][1] = Ph[i1];
            ah[mi][2] = Ph[i0 + 4]; ah[mi][3] = Ph[i1 + 4];
            al[mi][0] = Pl[i0];     al[mi][1] = Pl[i1];
            al[mi][2] = Pl[i0 + 4]; al[mi][3] = Pl[i1 + 4];
        }
#pragma unroll
        for (int ni = 0; ni < 4; ni++) {
            const int n = c0 + ni * 8 + qr;
            const int ib = n * PITCH32 + kw;    // Q[n][k] == Q[k][n] (symmetric)
            bh[ni][0] = Qh[ib]; bh[ni][1] = Qh[ib + 4];
            bl[ni][0] = Ql[ib]; bl[ni][1] = Ql[ib + 4];
        }
#pragma unroll
        for (int mi = 0; mi < 4; mi++)
#pragma unroll
            for (int ni = 0; ni < 4; ni++) {
                mma16816(acc[mi][ni], ah[mi], bh[ni]);
                mma16816(acc[mi][ni], ah[mi], bl[ni]);
                mma16816(acc[mi][ni], al[mi], bh[ni]);
            }
    }
}

__device__ __forceinline__ void acc_zero(float acc[4][4][4]) {
#pragma unroll
    for (int i = 0; i < 4; i++)
#pragma unroll
        for (int j = 0; j < 4; j++)
#pragma unroll
            for (int q = 0; q < 4; q++) acc[i][j][q] = 0.f;
}

// Write v = alpha*acc + beta*I back to an operand pair (hi/lo split).
__device__ __forceinline__ void epi_split(const float acc[4][4][4],
                                          uint32_t* __restrict__ Bh,
                                          uint32_t* __restrict__ Bl,
                                          float alpha, float beta, int r0,
                                          int c0, int lane) {
    const int qr = lane >> 2, cp = (lane & 3) * 2;
#pragma unroll
    for (int mi = 0; mi < 4; mi++)
#pragma unroll
        for (int ni = 0; ni < 4; ni++) {
            const int col = c0 + ni * 8 + cp;
#pragma unroll
            for (int h = 0; h < 2; h++) {
                const int row = r0 + mi * 16 + qr + h * 8;
                float v0 = alpha * acc[mi][ni][2 * h];
                float v1 = alpha * acc[mi][ni][2 * h + 1];
                if (row == col)     v0 += beta;
                if (row == col + 1) v1 += beta;
                uint32_t hw, lw;
                split2(v0, v1, hw, lw);
                const int idx = row * PITCH32 + (col >> 1);
                Bh[idx] = hw;
                Bl[idx] = lw;
            }
        }
}

// Final: Out[row][col] = s * acc
__device__ __forceinline__ void epi_out(const float acc[4][4][4],
                                        float* __restrict__ Ob, float s, int r0,
                                        int c0, int lane) {
    const int qr = lane >> 2, cp = (lane & 3) * 2;
#pragma unroll
    for (int mi = 0; mi < 4; mi++)
#pragma unroll
        for (int ni = 0; ni < 4; ni++) {
            const int col = c0 + ni * 8 + cp;
#pragma unroll
            for (int h = 0; h < 2; h++) {
                const int row = r0 + mi * 16 + qr + h * 8;
                *(float2*)(Ob + row * 128 + col) =
                    make_float2(s * acc[mi][ni][2 * h],
                                s * acc[mi][ni][2 * h + 1]);
            }
        }
}

__global__ void __launch_bounds__(NT, 1)
ns_hmma_kernel(const float* __restrict__ A, float* __restrict__ Out) {
    extern __shared__ uint32_t sm[];
    uint32_t* Yh = sm;
    uint32_t* Yl = sm + 128 * PITCH32;
    uint32_t* Zh = sm + 2 * 128 * PITCH32;
    uint32_t* Zl = sm + 3 * 128 * PITCH32;
    uint32_t* Th = sm + 4 * 128 * PITCH32;
    uint32_t* Tl = sm + 5 * 128 * PITCH32;
    __shared__ float red[8];

    const int tid = threadIdx.x, w = tid >> 5, lane = tid & 31;
    const int r0 = (w & 1) * 64, c0 = (w >> 1) * 32;
    const float* Ab = A + (size_t)blockIdx.x * 16384;
    float* Ob = Out + (size_t)blockIdx.x * 16384;

    // ---- Frobenius norm ----
    float ss = 0.f;
    const float4* A4 = (const float4*)Ab;
    for (int i = tid; i < 4096; i += NT) {
        float4 v = A4[i];
        ss = fmaf(v.x, v.x, fmaf(v.y, v.y, fmaf(v.z, v.z, fmaf(v.w, v.w, ss))));
    }
#pragma unroll
    for (int o = 16; o; o >>= 1) ss += __shfl_xor_sync(0xffffffffu, ss, o);
    if (lane == 0) red[w] = ss;
    __syncthreads();
    float tot = 0.f;
#pragma unroll
    for (int i = 0; i < 8; i++) tot += red[i];
    const float normA = sqrtf(tot);
    const float inv = 1.f / normA;

    // ---- Init: Y0 = A*inv (split); T1 = Z1 = 1.5I - 0.5*Y0 (split) ----
    {
        const int row = tid >> 1;
        const int chalf = (tid & 1) * 64;
#pragma unroll
        for (int g = 0; g < 8; g++) {
            const int col = chalf + g * 8;
            float4 a0 = *(const float4*)(Ab + row * 128 + col);
            float4 a1 = *(const float4*)(Ab + row * 128 + col + 4);
            float yv[8] = {a0.x * inv, a0.y * inv, a0.z * inv, a0.w * inv,
                           a1.x * inv, a1.y * inv, a1.z * inv, a1.w * inv};
#pragma unroll
            for (int jj = 0; jj < 4; jj++) {
                const int cc = col + 2 * jj;
                const int idx = row * PITCH32 + (cc >> 1);
                uint32_t hw, lw;
                split2(yv[2 * jj], yv[2 * jj + 1], hw, lw);
                Yh[idx] = hw; Yl[idx] = lw;
                float t0 = -0.5f * yv[2 * jj]     + (row == cc     ? 1.5f : 0.f);
                float t1 = -0.5f * yv[2 * jj + 1] + (row == cc + 1 ? 1.5f : 0.f);
                split2(t0, t1, hw, lw);
                Th[idx] = hw; Tl[idx] = lw;
                Zh[idx] = hw; Zl[idx] = lw;
            }
        }
    }
    __syncthreads();

    float acc[4][4][4];

    // ---- iter 1 (reduced): Y = Y @ T1 ----
    acc_zero(acc);
    mm_full(Yh, Yl, Th, Tl, acc, r0, c0, lane);
    __syncthreads();
    epi_split(acc, Yh, Yl, 1.f, 0.f, r0, c0, lane);
    __syncthreads();

    // ---- iters 2..5 ----
#pragma unroll 1
    for (int it = 1; it < 5; ++it) {
        // T = 1.5I - 0.5*(Z @ Y)
        acc_zero(acc);
        mm_full(Zh, Zl, Yh, Yl, acc, r0, c0, lane);
        __syncthreads();
        epi_split(acc, Th, Tl, -0.5f, 1.5f, r0, c0, lane);
        __syncthreads();

        // Y = Y @ T
        acc_zero(acc);
        mm_full(Yh, Yl, Th, Tl, acc, r0, c0, lane);
        __syncthreads();
        if (it < 4) {
            epi_split(acc, Yh, Yl, 1.f, 0.f, r0, c0, lane);
            __syncthreads();
            // Z = T @ Z
            acc_zero(acc);
            mm_full(Th, Tl, Zh, Zl, acc, r0, c0, lane);
            __syncthreads();
            epi_split(acc, Zh, Zl, 1.f, 0.f, r0, c0, lane);
            __syncthreads();
        } else {
            epi_out(acc, Ob, sqrtf(normA), r0, c0, lane);
        }
    }
}

extern "C" void kernel_launch(void* const* d_in, const int* in_sizes, int n_in,
                              void* d_out, int out_size) {
    const float* A = (const float*)d_in[0];
    float* out = (float*)d_out;
    const int nbatch = in_sizes[0] / (NMAT * NMAT);   // 1024
    const size_t smem = 6 * 128 * PITCH * sizeof(__nv_bfloat16);  // 208896 B
    cudaFuncSetAttribute(ns_hmma_kernel,
                         cudaFuncAttributeMaxDynamicSharedMemorySize, (int)smem);
    ns_hmma_kernel<<<nbatch, NT, smem>>>(A, out);
}

// round 4
// speedup vs baseline: 2.8374x; 1.1657x over previous
#include <cuda_runtime.h>
#include <cuda_bf16.h>
#include <cstdint>

// Batched Newton-Schulz matrix sqrt: 1024 x (128x128 fp32), 5 iterations.
// Warp-level mma.sync bf16, fp32 via hi+lo split (3 products: hh+hl+lh).
// Symmetry of all iterates lets B-fragments read rows (no transpose).
// 16 warps / CTA, 32x32 warp tiles; Y@T and T@Z merged into one MMA phase.

#define NMAT 128
#define NT 512
#define PITCH32 68   // u32 words per row (272B pitch -> conflict-free)

__device__ __forceinline__ void mma16816(float* d, const uint32_t* a,
                                         const uint32_t* b) {
    asm volatile(
        "mma.sync.aligned.m16n8k16.row.col.f32.bf16.bf16.f32 "
        "{%0,%1,%2,%3}, {%4,%5,%6,%7}, {%8,%9}, {%0,%1,%2,%3};"
        : "+f"(d[0]), "+f"(d[1]), "+f"(d[2]), "+f"(d[3])
        : "r"(a[0]), "r"(a[1]), "r"(a[2]), "r"(a[3]), "r"(b[0]), "r"(b[1]));
}

// Fast split: hw = {lo:bf16(v0), hi:bf16(v1)}, lw = residual pair.
__device__ __forceinline__ void split2f(float v0, float v1, uint32_t& hw,
                                        uint32_t& lw) {
    asm("cvt.rn.bf16x2.f32 %0, %1, %2;" : "=r"(hw) : "f"(v1), "f"(v0));
    float h0 = __uint_as_float(hw << 16);
    float h1 = __uint_as_float(hw & 0xffff0000u);
    float l0 = v0 - h0, l1 = v1 - h1;
    asm("cvt.rn.bf16x2.f32 %0, %1, %2;" : "=r"(lw) : "f"(l1), "f"(l0));
}

// acc += Ph@Qh + Ph@Ql + Pl@Qh over K=128; warp tile rows [r0,r0+32) x cols [c0,c0+32)
__device__ __forceinline__ void mm_tile(const uint32_t* __restrict__ Ph,
                                        const uint32_t* __restrict__ Pl,
                                        const uint32_t* __restrict__ Qh,
                                        const uint32_t* __restrict__ Ql,
                                        float acc[2][4][4], int r0, int c0,
                                        int lane) {
    const int qr = lane >> 2;
    const int kp = lane & 3;
#pragma unroll
    for (int k0 = 0; k0 < 8; k0++) {
        const int kw = k0 * 8 + kp;
        uint32_t ah[2][4], al[2][4], bh[4][2], bl[4][2];
#pragma unroll
        for (int mi = 0; mi < 2; mi++) {
            const int r = r0 + mi * 16 + qr;
            const int i0 = r * PITCH32 + kw;
            const int i1 = (r + 8) * PITCH32 + kw;
            ah[mi][0] = Ph[i0];     ah[mi][1] = Ph[i1];
            ah[mi][2] = Ph[i0 + 4]; ah[mi][3] = Ph[i1 + 4];
            al[mi][0] = Pl[i0];     al[mi][1] = Pl[i1];
            al[mi][2] = Pl[i0 + 4]; al[mi][3] = Pl[i1 + 4];
        }
#pragma unroll
        for (int ni = 0; ni < 4; ni++) {
            const int n = c0 + ni * 8 + qr;          // Q[n][k] == Q[k][n]
            const int ib = n * PITCH32 + kw;
            bh[ni][0] = Qh[ib]; bh[ni][1] = Qh[ib + 4];
            bl[ni][0] = Ql[ib]; bl[ni][1] = Ql[ib + 4];
        }
#pragma unroll
        for (int mi = 0; mi < 2; mi++)
#pragma unroll
            for (int ni = 0; ni < 4; ni++) {
                mma16816(acc[mi][ni], ah[mi], bh[ni]);
                mma16816(acc[mi][ni], ah[mi], bl[ni]);
                mma16816(acc[mi][ni], al[mi], bh[ni]);
            }
    }
}

__device__ __forceinline__ void acc_zero(float acc[2][4][4]) {
#pragma unroll
    for (int i = 0; i < 2; i++)
#pragma unroll
        for (int j = 0; j < 4; j++)
#pragma unroll
            for (int q = 0; q < 4; q++) acc[i][j][q] = 0.f;
}

// Write v = alpha*acc + beta*I to hi/lo operand pair.
__device__ __forceinline__ void epi_split(const float acc[2][4][4],
                                          uint32_t* __restrict__ Bh,
                                          uint32_t* __restrict__ Bl,
                                          float alpha, float beta, int r0,
                                          int c0, int lane) {
    const int qr = lane >> 2, cp = (lane & 3) * 2;
#pragma unroll
    for (int mi = 0; mi < 2; mi++)
#pragma unroll
        for (int ni = 0; ni < 4; ni++) {
            const int col = c0 + ni * 8 + cp;
#pragma unroll
            for (int h = 0; h < 2; h++) {
                const int row = r0 + mi * 16 + qr + h * 8;
                float v0 = alpha * acc[mi][ni][2 * h];
                float v1 = alpha * acc[mi][ni][2 * h + 1];
                if (row == col)     v0 += beta;
                if (row == col + 1) v1 += beta;
                uint32_t hw, lw;
                split2f(v0, v1, hw, lw);
                const int idx = row * PITCH32 + (col >> 1);
                Bh[idx] = hw;
                Bl[idx] = lw;
            }
        }
}

__device__ __forceinline__ void epi_out(const float acc[2][4][4],
                                        float* __restrict__ Ob, float s, int r0,
                                        int c0, int lane) {
    const int qr = lane >> 2, cp = (lane & 3) * 2;
#pragma unroll
    for (int mi = 0; mi < 2; mi++)
#pragma unroll
        for (int ni = 0; ni < 4; ni++) {
            const int col = c0 + ni * 8 + cp;
#pragma unroll
            for (int h = 0; h < 2; h++) {
                const int row = r0 + mi * 16 + qr + h * 8;
                *(float2*)(Ob + row * 128 + col) =
                    make_float2(s * acc[mi][ni][2 * h],
                                s * acc[mi][ni][2 * h + 1]);
            }
        }
}

__global__ void __launch_bounds__(NT, 1)
ns_hmma2_kernel(const float* __restrict__ A, float* __restrict__ Out) {
    extern __shared__ uint32_t sm[];
    uint32_t* Yh = sm;
    uint32_t* Yl = sm + 128 * PITCH32;
    uint32_t* Zh = sm + 2 * 128 * PITCH32;
    uint32_t* Zl = sm + 3 * 128 * PITCH32;
    uint32_t* Th = sm + 4 * 128 * PITCH32;
    uint32_t* Tl = sm + 5 * 128 * PITCH32;
    __shared__ float red[16];

    const int tid = threadIdx.x, w = tid >> 5, lane = tid & 31;
    const int r0 = (w & 3) * 32, c0 = (w >> 2) * 32;
    const float* Ab = A + (size_t)blockIdx.x * 16384;
    float* Ob = Out + (size_t)blockIdx.x * 16384;

    // ---- Frobenius norm ----
    float ss = 0.f;
    const float4* A4 = (const float4*)Ab;
    for (int i = tid; i < 4096; i += NT) {
        float4 v = A4[i];
        ss = fmaf(v.x, v.x, fmaf(v.y, v.y, fmaf(v.z, v.z, fmaf(v.w, v.w, ss))));
    }
#pragma unroll
    for (int o = 16; o; o >>= 1) ss += __shfl_xor_sync(0xffffffffu, ss, o);
    if (lane == 0) red[w] = ss;
    __syncthreads();
    float tot = 0.f;
#pragma unroll
    for (int i = 0; i < 16; i++) tot += red[i];
    const float normA = sqrtf(tot);
    const float inv = 1.f / normA;

    // ---- Init: Y0 = A*inv (split); T1 = Z1 = 1.5I - 0.5*Y0 (split) ----
    {
        const int row = tid >> 2;
        const int cq = (tid & 3) * 32;
#pragma unroll
        for (int g = 0; g < 4; g++) {
            const int col = cq + g * 8;
            float4 a0 = *(const float4*)(Ab + row * 128 + col);
            float4 a1 = *(const float4*)(Ab + row * 128 + col + 4);
            float yv[8] = {a0.x * inv, a0.y * inv, a0.z * inv, a0.w * inv,
                           a1.x * inv, a1.y * inv, a1.z * inv, a1.w * inv};
#pragma unroll
            for (int jj = 0; jj < 4; jj++) {
                const int cc = col + 2 * jj;
                const int idx = row * PITCH32 + (cc >> 1);
                uint32_t hw, lw;
                split2f(yv[2 * jj], yv[2 * jj + 1], hw, lw);
                Yh[idx] = hw; Yl[idx] = lw;
                float t0 = -0.5f * yv[2 * jj]     + (row == cc     ? 1.5f : 0.f);
                float t1 = -0.5f * yv[2 * jj + 1] + (row == cc + 1 ? 1.5f : 0.f);
                split2f(t0, t1, hw, lw);
                Th[idx] = hw; Tl[idx] = lw;
                Zh[idx] = hw; Zl[idx] = lw;
            }
        }
    }
    __syncthreads();

    float accA[2][4][4], accZ[2][4][4];

    // ---- iter 1 (reduced): Y = Y @ T1 ----
    acc_zero(accA);
    mm_tile(Yh, Yl, Th, Tl, accA, r0, c0, lane);
    __syncthreads();
    epi_split(accA, Yh, Yl, 1.f, 0.f, r0, c0, lane);
    __syncthreads();

    // ---- iters 2..5 ----
#pragma unroll 1
    for (int it = 1; it < 5; ++it) {
        // T = 1.5I - 0.5*(Z @ Y)
        acc_zero(accA);
        mm_tile(Zh, Zl, Yh, Yl, accA, r0, c0, lane);
        __syncthreads();
        epi_split(accA, Th, Tl, -0.5f, 1.5f, r0, c0, lane);
        __syncthreads();

        // Merged phase: Y = Y@T and (it<4) Z = T@Z
        acc_zero(accA);
        mm_tile(Yh, Yl, Th, Tl, accA, r0, c0, lane);
        if (it < 4) {
            acc_zero(accZ);
            mm_tile(Th, Tl, Zh, Zl, accZ, r0, c0, lane);
        }
        __syncthreads();
        if (it < 4) {
            epi_split(accA, Yh, Yl, 1.f, 0.f, r0, c0, lane);
            epi_split(accZ, Zh, Zl, 1.f, 0.f, r0, c0, lane);
            __syncthreads();
        } else {
            epi_out(accA, Ob, sqrtf(normA), r0, c0, lane);
        }
    }
}

extern "C" void kernel_launch(void* const* d_in, const int* in_sizes, int n_in,
                              void* d_out, int out_size) {
    const float* A = (const float*)d_in[0];
    float* out = (float*)d_out;
    const int nbatch = in_sizes[0] / (NMAT * NMAT);       // 1024
    const size_t smem = 6 * 128 * PITCH32 * sizeof(uint32_t);  // 208896 B
    cudaFuncSetAttribute(ns_hmma2_kernel,
                         cudaFuncAttributeMaxDynamicSharedMemorySize, (int)smem);
    ns_hmma2_kernel<<<nbatch, NT, smem>>>(A, out);
}

// round 5
// speedup vs baseline: 3.2857x; 1.1580x over previous
#include <cuda_runtime.h>
#include <cuda_bf16.h>
#include <cstdint>

// Batched Newton-Schulz matrix sqrt: 1024 x (128x128 fp32), 5 iterations.
// mma.sync bf16, fp32 via hi+lo split (3 products). All iterates symmetric
// and commuting (polynomials of A/||A||):
//   - B-fragments read rows (no transpose)
//   - outputs computed on lower-triangular tiles only, mirrored in epilogue
//   - Z update uses Z@T (== T@Z), sharing B=T with Y@T.

#define NMAT 128
#define NT 512
#define PITCH32 68   // u32 words per smem row (272B pitch, conflict-free)
#define PITCH16 136

__device__ __forceinline__ void mma16816(float* d, const uint32_t* a,
                                         const uint32_t* b) {
    asm volatile(
        "mma.sync.aligned.m16n8k16.row.col.f32.bf16.bf16.f32 "
        "{%0,%1,%2,%3}, {%4,%5,%6,%7}, {%8,%9}, {%0,%1,%2,%3};"
        : "+f"(d[0]), "+f"(d[1]), "+f"(d[2]), "+f"(d[3])
        : "r"(a[0]), "r"(a[1]), "r"(a[2]), "r"(a[3]), "r"(b[0]), "r"(b[1]));
}

__device__ __forceinline__ void split2f(float v0, float v1, uint32_t& hw,
                                        uint32_t& lw) {
    asm("cvt.rn.bf16x2.f32 %0, %1, %2;" : "=r"(hw) : "f"(v1), "f"(v0));
    float h0 = __uint_as_float(hw << 16);
    float h1 = __uint_as_float(hw & 0xffff0000u);
    float l0 = v0 - h0, l1 = v1 - h1;
    asm("cvt.rn.bf16x2.f32 %0, %1, %2;" : "=r"(lw) : "f"(l1), "f"(l0));
}

// acc += Ph@Qh + Ph@Ql + Pl@Qh over K=128; tile rows [r0,r0+32) x cols [c0,c0+32)
__device__ __forceinline__ void mm_tile(const uint32_t* __restrict__ Ph,
                                        const uint32_t* __restrict__ Pl,
                                        const uint32_t* __restrict__ Qh,
                                        const uint32_t* __restrict__ Ql,
                                        float acc[2][4][4], int r0, int c0,
                                        int lane) {
    const int qr = lane >> 2;
    const int kp = lane & 3;
#pragma unroll
    for (int k0 = 0; k0 < 8; k0++) {
        const int kw = k0 * 8 + kp;
        uint32_t ah[2][4], al[2][4], bh[4][2], bl[4][2];
#pragma unroll
        for (int mi = 0; mi < 2; mi++) {
            const int r = r0 + mi * 16 + qr;
            const int i0 = r * PITCH32 + kw;
            const int i1 = (r + 8) * PITCH32 + kw;
            ah[mi][0] = Ph[i0];     ah[mi][1] = Ph[i1];
            ah[mi][2] = Ph[i0 + 4]; ah[mi][3] = Ph[i1 + 4];
            al[mi][0] = Pl[i0];     al[mi][1] = Pl[i1];
            al[mi][2] = Pl[i0 + 4]; al[mi][3] = Pl[i1 + 4];
        }
#pragma unroll
        for (int ni = 0; ni < 4; ni++) {
            const int n = c0 + ni * 8 + qr;      // Q[n][k] == Q[k][n]
            const int ib = n * PITCH32 + kw;
            bh[ni][0] = Qh[ib]; bh[ni][1] = Qh[ib + 4];
            bl[ni][0] = Ql[ib]; bl[ni][1] = Ql[ib + 4];
        }
#pragma unroll
        for (int mi = 0; mi < 2; mi++)
#pragma unroll
            for (int ni = 0; ni < 4; ni++) {
                mma16816(acc[mi][ni], ah[mi], bh[ni]);
                mma16816(acc[mi][ni], ah[mi], bl[ni]);
                mma16816(acc[mi][ni], al[mi], bh[ni]);
            }
    }
}

__device__ __forceinline__ void acc_zero(float acc[2][4][4]) {
#pragma unroll
    for (int i = 0; i < 2; i++)
#pragma unroll
        for (int j = 0; j < 4; j++)
#pragma unroll
            for (int q = 0; q < 4; q++) acc[i][j][q] = 0.f;
}

// Write v = alpha*acc + beta*I to hi/lo pair; optionally mirror to (col,row).
__device__ __forceinline__ void epi_split(const float acc[2][4][4],
                                          uint32_t* __restrict__ Bh,
                                          uint32_t* __restrict__ Bl,
                                          float alpha, float beta, int r0,
                                          int c0, int lane, bool mir) {
    const int qr = lane >> 2, cp = (lane & 3) * 2;
    uint16_t* H16 = (uint16_t*)Bh;
    uint16_t* L16 = (uint16_t*)Bl;
#pragma unroll
    for (int mi = 0; mi < 2; mi++)
#pragma unroll
        for (int ni = 0; ni < 4; ni++) {
            const int col = c0 + ni * 8 + cp;
#pragma unroll
            for (int h = 0; h < 2; h++) {
                const int row = r0 + mi * 16 + qr + h * 8;
                float v0 = alpha * acc[mi][ni][2 * h];
                float v1 = alpha * acc[mi][ni][2 * h + 1];
                if (row == col)     v0 += beta;
                if (row == col + 1) v1 += beta;
                uint32_t hw, lw;
                split2f(v0, v1, hw, lw);
                const int idx = row * PITCH32 + (col >> 1);
                Bh[idx] = hw;
                Bl[idx] = lw;
                if (mir) {
                    H16[col * PITCH16 + row]       = (uint16_t)hw;
                    H16[(col + 1) * PITCH16 + row] = (uint16_t)(hw >> 16);
                    L16[col * PITCH16 + row]       = (uint16_t)lw;
                    L16[(col + 1) * PITCH16 + row] = (uint16_t)(lw >> 16);
                }
            }
        }
}

__device__ __forceinline__ void epi_out(const float acc[2][4][4],
                                        float* __restrict__ Ob, float s, int r0,
                                        int c0, int lane) {
    const int qr = lane >> 2, cp = (lane & 3) * 2;
#pragma unroll
    for (int mi = 0; mi < 2; mi++)
#pragma unroll
        for (int ni = 0; ni < 4; ni++) {
            const int col = c0 + ni * 8 + cp;
#pragma unroll
            for (int h = 0; h < 2; h++) {
                const int row = r0 + mi * 16 + qr + h * 8;
                *(float2*)(Ob + row * 128 + col) =
                    make_float2(s * acc[mi][ni][2 * h],
                                s * acc[mi][ni][2 * h + 1]);
            }
        }
}

// Lower-triangular 32x32 tile list (10 tiles)
__device__ __constant__ int LTI[10] = {0, 1, 1, 2, 2, 2, 3, 3, 3, 3};
__device__ __constant__ int LTJ[10] = {0, 0, 1, 0, 1, 2, 0, 1, 2, 3};

__global__ void __launch_bounds__(NT, 1)
ns_tri_kernel(const float* __restrict__ A, float* __restrict__ Out) {
    extern __shared__ uint32_t sm[];
    uint32_t* Yh = sm;
    uint32_t* Yl = sm + 128 * PITCH32;
    uint32_t* Zh = sm + 2 * 128 * PITCH32;
    uint32_t* Zl = sm + 3 * 128 * PITCH32;
    uint32_t* Th = sm + 4 * 128 * PITCH32;
    uint32_t* Tl = sm + 5 * 128 * PITCH32;
    __shared__ float red[16];

    const int tid = threadIdx.x, w = tid >> 5, lane = tid & 31;
    const float* Ab = A + (size_t)blockIdx.x * 16384;
    float* Ob = Out + (size_t)blockIdx.x * 16384;

    // Triangular tile coords for this warp (P1 / iter1, warps 0..9)
    const int tr0 = (w < 10) ? LTI[w] * 32 : 0;
    const int tc0 = (w < 10) ? LTJ[w] * 32 : 0;
    const bool tmir = (w < 10) && (tr0 != tc0);
    // P2 task A: w<10 -> Y tile L[w]; w>=10 -> Z tile L[w-10]
    const int a_idx = (w < 10) ? w : (w - 10);
    const int ar0 = LTI[a_idx] * 32, ac0 = LTJ[a_idx] * 32;
    const bool amir = (ar0 != ac0);
    // P2 task B (w<4): Z tile L[w+6]
    const int br0 = (w < 4) ? LTI[w + 6] * 32 : 0;
    const int bc0 = (w < 4) ? LTJ[w + 6] * 32 : 0;
    // full-grid tile (last Y@T)
    const int fr0 = (w & 3) * 32, fc0 = (w >> 2) * 32;

    // ---- Frobenius norm ----
    float ss = 0.f;
    const float4* A4 = (const float4*)Ab;
    for (int i = tid; i < 4096; i += NT) {
        float4 v = A4[i];
        ss = fmaf(v.x, v.x, fmaf(v.y, v.y, fmaf(v.z, v.z, fmaf(v.w, v.w, ss))));
    }
#pragma unroll
    for (int o = 16; o; o >>= 1) ss += __shfl_xor_sync(0xffffffffu, ss, o);
    if (lane == 0) red[w] = ss;
    __syncthreads();
    float tot = 0.f;
#pragma unroll
    for (int i = 0; i < 16; i++) tot += red[i];
    const float normA = sqrtf(tot);
    const float inv = 1.f / normA;

    // ---- Init: Y0 = A*inv; T1 = Z1 = 1.5I - 0.5*Y0 (all split) ----
    {
        const int row = tid >> 2;
        const int cq = (tid & 3) * 32;
#pragma unroll
        for (int g = 0; g < 4; g++) {
            const int col = cq + g * 8;
            float4 a0 = *(const float4*)(Ab + row * 128 + col);
            float4 a1 = *(const float4*)(Ab + row * 128 + col + 4);
            float yv[8] = {a0.x * inv, a0.y * inv, a0.z * inv, a0.w * inv,
                           a1.x * inv, a1.y * inv, a1.z * inv, a1.w * inv};
#pragma unroll
            for (int jj = 0; jj < 4; jj++) {
                const int cc = col + 2 * jj;
                const int idx = row * PITCH32 + (cc >> 1);
                uint32_t hw, lw;
                split2f(yv[2 * jj], yv[2 * jj + 1], hw, lw);
                Yh[idx] = hw; Yl[idx] = lw;
                float t0 = -0.5f * yv[2 * jj]     + (row == cc     ? 1.5f : 0.f);
                float t1 = -0.5f * yv[2 * jj + 1] + (row == cc + 1 ? 1.5f : 0.f);
                split2f(t0, t1, hw, lw);
                Th[idx] = hw; Tl[idx] = lw;
                Zh[idx] = hw; Zl[idx] = lw;
            }
        }
    }
    __syncthreads();

    float accA[2][4][4], accZ[2][4][4];

    // ---- iter 1 (reduced): Y = Y @ T1, triangular ----
    if (w < 10) {
        acc_zero(accA);
        mm_tile(Yh, Yl, Th, Tl, accA, tr0, tc0, lane);
    }
    __syncthreads();
    if (w < 10) epi_split(accA, Yh, Yl, 1.f, 0.f, tr0, tc0, lane, tmir);
    __syncthreads();

    // ---- iters 2..5 ----
#pragma unroll 1
    for (int it = 1; it < 5; ++it) {
        // P1: T = 1.5I - 0.5*(Z @ Y), triangular; epi T immediately
        if (w < 10) {
            acc_zero(accA);
            mm_tile(Zh, Zl, Yh, Yl, accA, tr0, tc0, lane);
            epi_split(accA, Th, Tl, -0.5f, 1.5f, tr0, tc0, lane, tmir);
        }
        __syncthreads();

        if (it < 4) {
            // P2: Y = Y@T (tiles via warps 0..9) and Z = Z@T (rest + extras)
            acc_zero(accA);
            if (w < 10) mm_tile(Yh, Yl, Th, Tl, accA, ar0, ac0, lane);
            else        mm_tile(Zh, Zl, Th, Tl, accA, ar0, ac0, lane);
            if (w < 4) {
                acc_zero(accZ);
                mm_tile(Zh, Zl, Th, Tl, accZ, br0, bc0, lane);
            }
            __syncthreads();
            if (w < 10) epi_split(accA, Yh, Yl, 1.f, 0.f, ar0, ac0, lane, amir);
            else        epi_split(accA, Zh, Zl, 1.f, 0.f, ar0, ac0, lane, amir);
            if (w < 4)  epi_split(accZ, Zh, Zl, 1.f, 0.f, br0, bc0, lane, true);
            __syncthreads();
        } else {
            // Last: Y5 = Y@T, full grid, straight to GMEM
            acc_zero(accA);
            mm_tile(Yh, Yl, Th, Tl, accA, fr0, fc0, lane);
            epi_out(accA, Ob, sqrtf(normA), fr0, fc0, lane);
        }
    }
}

extern "C" void kernel_launch(void* const* d_in, const int* in_sizes, int n_in,
                              void* d_out, int out_size) {
    const float* A = (const float*)d_in[0];
    float* out = (float*)d_out;
    const int nbatch = in_sizes[0] / (NMAT * NMAT);            // 1024
    const size_t smem = 6 * 128 * PITCH32 * sizeof(uint32_t);  // 208896 B
    cudaFuncSetAttribute(ns_tri_kernel,
                         cudaFuncAttributeMaxDynamicSharedMemorySize, (int)smem);
    ns_tri_kernel<<<nbatch, NT, smem>>>(A, out);
}

// round 7
// speedup vs baseline: 3.4931x; 1.0631x over previous
#include <cuda_runtime.h>
#include <cuda_bf16.h>
#include <cstdint>

// Batched Newton-Schulz matrix sqrt: 1024 x (128x128 fp32), 5 iterations.
// mma.sync bf16 + ldmatrix; fp32 via hi+lo split (hh+hl+lh). All iterates
// symmetric & commuting => B-frags read rows; outputs lower-tri + mirror;
// Z update as Z@T shares B(=T) fragments with Y@T in one fused k-loop.

#define NMAT 128
#define NT 512
#define PITCH32 68      // u32 words per smem row
#define PITCHB 272      // bytes per smem row
#define PITCH16 136

__device__ __forceinline__ void mma16816(float* d, const uint32_t* a,
                                         const uint32_t* b) {
    asm volatile(
        "mma.sync.aligned.m16n8k16.row.col.f32.bf16.bf16.f32 "
        "{%0,%1,%2,%3}, {%4,%5,%6,%7}, {%8,%9}, {%0,%1,%2,%3};"
        : "+f"(d[0]), "+f"(d[1]), "+f"(d[2]), "+f"(d[3])
        : "r"(a[0]), "r"(a[1]), "r"(a[2]), "r"(a[3]), "r"(b[0]), "r"(b[1]));
}

#define LDSM4(r_, a_)                                                         \
    asm volatile("ldmatrix.sync.aligned.m8n8.x4.shared.b16 {%0,%1,%2,%3}, [%4];" \
                 : "=r"((r_)[0]), "=r"((r_)[1]), "=r"((r_)[2]), "=r"((r_)[3])  \
                 : "r"(a_))

__device__ __forceinline__ uint32_t sp(const void* p) {
    return (uint32_t)__cvta_generic_to_shared(p);
}

__device__ __forceinline__ void split2f(float v0, float v1, uint32_t& hw,
                                        uint32_t& lw) {
    asm("cvt.rn.bf16x2.f32 %0, %1, %2;" : "=r"(hw) : "f"(v1), "f"(v0));
    float h0 = __uint_as_float(hw << 16);
    float h1 = __uint_as_float(hw & 0xffff0000u);
    float l0 = v0 - h0, l1 = v1 - h1;
    asm("cvt.rn.bf16x2.f32 %0, %1, %2;" : "=r"(lw) : "f"(l1), "f"(l0));
}

__device__ __forceinline__ void zero4(float a[4][4]) {
#pragma unroll
    for (int i = 0; i < 4; i++)
#pragma unroll
        for (int j = 0; j < 4; j++) a[i][j] = 0.f;
}

// Per-lane fragment byte offsets (ldmatrix octet addressing)
__device__ __forceinline__ uint32_t a_off(int r0, int lane) {
    return (uint32_t)((r0 + (lane & 7) + ((lane >> 3) & 1) * 8) * PITCHB +
                      (lane >> 4) * 16);
}
__device__ __forceinline__ uint32_t b_off(int c0, int lane) {
    return (uint32_t)((c0 + (lane & 7) + (lane >> 4) * 8) * PITCHB +
                      ((lane >> 3) & 1) * 16);
}

// Single product: acc += Ph@Qh + Ph@Ql + Pl@Qh; m16 rows r0, n32 cols c0.
__device__ __forceinline__ void mm_half(const uint32_t* Ph, const uint32_t* Pl,
                                        const uint32_t* Qh, const uint32_t* Ql,
                                        float acc[4][4], int r0, int c0,
                                        int lane) {
    const uint32_t ao = a_off(r0, lane), bo = b_off(c0, lane);
    uint32_t pah = sp(Ph) + ao, pal = sp(Pl) + ao;
    uint32_t qh0 = sp(Qh) + bo, qh1 = qh0 + 16 * PITCHB;
    uint32_t ql0 = sp(Ql) + bo, ql1 = ql0 + 16 * PITCHB;
#pragma unroll
    for (int k0 = 0; k0 < 8; k0++) {
        uint32_t ah[4], al[4], bh[8], bl[8];
        LDSM4(ah, pah); LDSM4(al, pal);
        LDSM4(bh, qh0); LDSM4(bh + 4, qh1);
        LDSM4(bl, ql0); LDSM4(bl + 4, ql1);
        pah += 32; pal += 32; qh0 += 32; qh1 += 32; ql0 += 32; ql1 += 32;
#pragma unroll
        for (int ni = 0; ni < 4; ni++) {
            mma16816(acc[ni], ah, bh + ni * 2);
            mma16816(acc[ni], ah, bl + ni * 2);
            mma16816(acc[ni], al, bh + ni * 2);
        }
    }
}

// Paired products sharing B: accY += Y@T, accZ += Z@T (same tile coords).
__device__ __forceinline__ void mm_pair(const uint32_t* Yh, const uint32_t* Yl,
                                        const uint32_t* Zh, const uint32_t* Zl,
                                        const uint32_t* Th, const uint32_t* Tl,
                                        float accY[4][4], float accZ[4][4],
                                        int r0, int c0, int lane) {
    const uint32_t ao = a_off(r0, lane), bo = b_off(c0, lane);
    uint32_t pyh = sp(Yh) + ao, pyl = sp(Yl) + ao;
    uint32_t pzh = sp(Zh) + ao, pzl = sp(Zl) + ao;
    uint32_t qh0 = sp(Th) + bo, qh1 = qh0 + 16 * PITCHB;
    uint32_t ql0 = sp(Tl) + bo, ql1 = ql0 + 16 * PITCHB;
#pragma unroll
    for (int k0 = 0; k0 < 8; k0++) {
        uint32_t ayh[4], ayl[4], azh[4], azl[4], bh[8], bl[8];
        LDSM4(ayh, pyh); LDSM4(ayl, pyl);
        LDSM4(azh, pzh); LDSM4(azl, pzl);
        LDSM4(bh, qh0); LDSM4(bh + 4, qh1);
        LDSM4(bl, ql0); LDSM4(bl + 4, ql1);
        pyh += 32; pyl += 32; pzh += 32; pzl += 32;
        qh0 += 32; qh1 += 32; ql0 += 32; ql1 += 32;
#pragma unroll
        for (int ni = 0; ni < 4; ni++) {
            mma16816(accY[ni], ayh, bh + ni * 2);
            mma16816(accY[ni], ayh, bl + ni * 2);
            mma16816(accY[ni], ayl, bh + ni * 2);
            mma16816(accZ[ni], azh, bh + ni * 2);
            mma16816(accZ[ni], azh, bl + ni * 2);
            mma16816(accZ[ni], azl, bh + ni * 2);
        }
    }
}

// v = alpha*acc + beta*I -> hi/lo pair; optional mirror to transposed pos.
__device__ __forceinline__ void epi_half(const float acc[4][4],
                                         uint32_t* __restrict__ Bh,
                                         uint32_t* __restrict__ Bl, float alpha,
                                         float beta, int r0, int c0, int lane,
                                         bool mir) {
    const int qr = lane >> 2, cp = (lane & 3) * 2;
    uint16_t* H16 = (uint16_t*)Bh;
    uint16_t* L16 = (uint16_t*)Bl;
#pragma unroll
    for (int ni = 0; ni < 4; ni++) {
        const int col = c0 + ni * 8 + cp;
#pragma unroll
        for (int h = 0; h < 2; h++) {
            const int row = r0 + qr + h * 8;
            float v0 = alpha * acc[ni][2 * h]     + ((row == col)     ? beta : 0.f);
            float v1 = alpha * acc[ni][2 * h + 1] + ((row == col + 1) ? beta : 0.f);
            uint32_t hw, lw;
            split2f(v0, v1, hw, lw);
            const int idx = row * PITCH32 + (col >> 1);
            Bh[idx] = hw;
            Bl[idx] = lw;
            if (mir) {
                H16[col * PITCH16 + row]       = (uint16_t)hw;
                H16[(col + 1) * PITCH16 + row] = (uint16_t)(hw >> 16);
                L16[col * PITCH16 + row]       = (uint16_t)lw;
                L16[(col + 1) * PITCH16 + row] = (uint16_t)(lw >> 16);
            }
        }
    }
}

__device__ __forceinline__ void epi_out_half(const float acc[4][4],
                                             float* __restrict__ Ob, float s,
                                             int r0, int c0, int lane) {
    const int qr = lane >> 2, cp = (lane & 3) * 2;
#pragma unroll
    for (int ni = 0; ni < 4; ni++) {
        const int col = c0 + ni * 8 + cp;
#pragma unroll
        for (int h = 0; h < 2; h++) {
            const int row = r0 + qr + h * 8;
            *(float2*)(Ob + row * 128 + col) =
                make_float2(s * acc[ni][2 * h], s * acc[ni][2 * h + 1]);
        }
    }
}

__device__ __constant__ int LTI[10] = {0, 1, 1, 2, 2, 2, 3, 3, 3, 3};
__device__ __constant__ int LTJ[10] = {0, 0, 1, 0, 1, 2, 0, 1, 2, 3};

__global__ void __launch_bounds__(NT, 1)
ns_ldsm_kernel(const float* __restrict__ A, float* __restrict__ Out) {
    extern __shared__ uint32_t sm[];
    uint32_t* Yh = sm;
    uint32_t* Yl = sm + 128 * PITCH32;
    uint32_t* Zh = sm + 2 * 128 * PITCH32;
    uint32_t* Zl = sm + 3 * 128 * PITCH32;
    uint32_t* Th = sm + 4 * 128 * PITCH32;
    uint32_t* Tl = sm + 5 * 128 * PITCH32;
    __shared__ float red[16];

    const int tid = threadIdx.x, w = tid >> 5, lane = tid & 31;
    const float* Ab = A + (size_t)blockIdx.x * 16384;
    float* Ob = Out + (size_t)blockIdx.x * 16384;

    // --- Task coords ---
    // P1 / iter1: 20 halves; warp w -> task w; w<4 also task w+16.
    const int p0 = w % 10, h0 = w / 10;
    const int P1r0 = LTI[p0] * 32 + h0 * 16, P1c0 = LTJ[p0] * 32;
    const bool P1m0 = (LTI[p0] != LTJ[p0]);
    const bool has1 = (w < 4);
    const int p1 = w + 6;  // task w+16 -> p=w+6, h=1
    const int P1r1 = (has1 ? LTI[p1] : 0) * 32 + 16;
    const int P1c1 = (has1 ? LTJ[p1] : 0) * 32;
    const bool P1m1 = has1 && (LTI[p1] != LTJ[p1]);
    // P2 pair task w (0..15)
    const int pp = w % 10, ph = w / 10;
    const int P2r = LTI[pp] * 32 + ph * 16, P2c = LTJ[pp] * 32;
    const bool P2m = (LTI[pp] != LTJ[pp]);
    // P2 extra single (w>=8): task 16+(w&3); Y for w<12, Z for w>=12
    const int pe = 6 + (w & 3);
    const int P2er = LTI[pe] * 32 + 16, P2ec = LTJ[pe] * 32;
    const bool P2em = (LTI[pe] != LTJ[pe]);
    // last-iter full grid: tasks w and w+16; task t -> r=(t&7)*16, c=(t>>3)*32
    const int L0r = (w & 7) * 16, L0c = (w >> 3) * 32;
    const int L1r = L0r, L1c = L0c + 64;  // t+16: (t>>3)+2

    // ---- Frobenius norm ----
    float ss = 0.f;
    const float4* A4 = (const float4*)Ab;
    for (int i = tid; i < 4096; i += NT) {
        float4 v = A4[i];
        ss = fmaf(v.x, v.x, fmaf(v.y, v.y, fmaf(v.z, v.z, fmaf(v.w, v.w, ss))));
    }
#pragma unroll
    for (int o = 16; o; o >>= 1) ss += __shfl_xor_sync(0xffffffffu, ss, o);
    if (lane == 0) red[w] = ss;
    __syncthreads();
    float tot = 0.f;
#pragma unroll
    for (int i = 0; i < 16; i++) tot += red[i];
    const float normA = sqrtf(tot);
    const float inv = 1.f / normA;

    // ---- Init: Y0 = A*inv; T1 = Z1 = 1.5I - 0.5*Y0 ----
    {
        const int row = tid >> 2;
        const int cq = (tid & 3) * 32;
#pragma unroll
        for (int g = 0; g < 4; g++) {
            const int col = cq + g * 8;
            float4 a0 = *(const float4*)(Ab + row * 128 + col);
            float4 a1 = *(const float4*)(Ab + row * 128 + col + 4);
            float yv[8] = {a0.x * inv, a0.y * inv, a0.z * inv, a0.w * inv,
                           a1.x * inv, a1.y * inv, a1.z * inv, a1.w * inv};
#pragma unroll
            for (int jj = 0; jj < 4; jj++) {
                const int cc = col + 2 * jj;
                const int idx = row * PITCH32 + (cc >> 1);
                uint32_t hw, lw;
                split2f(yv[2 * jj], yv[2 * jj + 1], hw, lw);
                Yh[idx] = hw; Yl[idx] = lw;
                float t0 = -0.5f * yv[2 * jj]     + (row == cc     ? 1.5f : 0.f);
                float t1 = -0.5f * yv[2 * jj + 1] + (row == cc + 1 ? 1.5f : 0.f);
                split2f(t0, t1, hw, lw);
                Th[idx] = hw; Tl[idx] = lw;
                Zh[idx] = hw; Zl[idx] = lw;
            }
        }
    }
    __syncthreads();

    // ---- iter 1 (reduced): Y = Y @ T1 ----
    {
        float a0[4][4], a1[4][4];
        zero4(a0);
        mm_half(Yh, Yl, Th, Tl, a0, P1r0, P1c0, lane);
        if (has1) {
            zero4(a1);
            mm_half(Yh, Yl, Th, Tl, a1, P1r1, P1c1, lane);
        }
        __syncthreads();
        epi_half(a0, Yh, Yl, 1.f, 0.f, P1r0, P1c0, lane, P1m0);
        if (has1) epi_half(a1, Yh, Yl, 1.f, 0.f, P1r1, P1c1, lane, P1m1);
        __syncthreads();
    }

    // ---- iters 2..5 ----
#pragma unroll 1
    for (int it = 1; it < 5; ++it) {
        // P1: T = 1.5I - 0.5*(Z @ Y); epi fused (T not a P1 operand)
        {
            float a0[4][4];
            zero4(a0);
            mm_half(Zh, Zl, Yh, Yl, a0, P1r0, P1c0, lane);
            epi_half(a0, Th, Tl, -0.5f, 1.5f, P1r0, P1c0, lane, P1m0);
            if (has1) {
                zero4(a0);
                mm_half(Zh, Zl, Yh, Yl, a0, P1r1, P1c1, lane);
                epi_half(a0, Th, Tl, -0.5f, 1.5f, P1r1, P1c1, lane, P1m1);
            }
        }
        __syncthreads();

        if (it < 4) {
            // P2: Y = Y@T and Z = Z@T (paired, shared B) + extra singles
            float ay[4][4], az[4][4], ae[4][4];
            zero4(ay); zero4(az);
            mm_pair(Yh, Yl, Zh, Zl, Th, Tl, ay, az, P2r, P2c, lane);
            if (w >= 8) {
                zero4(ae);
                if (w < 12) mm_half(Yh, Yl, Th, Tl, ae, P2er, P2ec, lane);
                else        mm_half(Zh, Zl, Th, Tl, ae, P2er, P2ec, lane);
            }
            __syncthreads();
            epi_half(ay, Yh, Yl, 1.f, 0.f, P2r, P2c, lane, P2m);
            epi_half(az, Zh, Zl, 1.f, 0.f, P2r, P2c, lane, P2m);
            if (w >= 8) {
                if (w < 12) epi_half(ae, Yh, Yl, 1.f, 0.f, P2er, P2ec, lane, P2em);
                else        epi_half(ae, Zh, Zl, 1.f, 0.f, P2er, P2ec, lane, P2em);
            }
            __syncthreads();
        } else {
            // Last: Y5 = Y@T full grid, straight to GMEM
            const float s = sqrtf(normA);
            float a0[4][4];
            zero4(a0);
            mm_half(Yh, Yl, Th, Tl, a0, L0r, L0c, lane);
            epi_out_half(a0, Ob, s, L0r, L0c, lane);
            zero4(a0);
            mm_half(Yh, Yl, Th, Tl, a0, L1r, L1c, lane);
            epi_out_half(a0, Ob, s, L1r, L1c, lane);
        }
    }
}

extern "C" void kernel_launch(void* const* d_in, const int* in_sizes, int n_in,
                              void* d_out, int out_size) {
    const float* A = (const float*)d_in[0];
    float* out = (float*)d_out;
    const int nbatch = in_sizes[0] / (NMAT * NMAT);            // 1024
    const size_t smem = 6 * 128 * PITCH32 * sizeof(uint32_t);  // 208896 B
    cudaFuncSetAttribute(ns_ldsm_kernel,
                         cudaFuncAttributeMaxDynamicSharedMemorySize, (int)smem);
    ns_ldsm_kernel<<<nbatch, NT, smem>>>(A, out);
}

// round 8
// speedup vs baseline: 3.6296x; 1.0391x over previous
#include <cuda_runtime.h>
#include <cuda_bf16.h>
#include <cstdint>

// Batched Newton-Schulz matrix sqrt: 1024 x (128x128 fp32), 5 iterations.
// mma.sync bf16 + ldmatrix, fp32 via hi+lo split (hh+hl+lh), triangular
// outputs + mirror (all iterates symmetric, commuting). 12 warps with
// register double-buffered k-loop (prefetch next fragments under MMAs).

#define NMAT 128
#define NT 384
#define PITCH32 68      // u32 words per smem row
#define PITCHB 272      // bytes per smem row
#define PITCH16 136

__device__ __forceinline__ void mma16816(float* d, const uint32_t* a,
                                         const uint32_t* b) {
    asm volatile(
        "mma.sync.aligned.m16n8k16.row.col.f32.bf16.bf16.f32 "
        "{%0,%1,%2,%3}, {%4,%5,%6,%7}, {%8,%9}, {%0,%1,%2,%3};"
        : "+f"(d[0]), "+f"(d[1]), "+f"(d[2]), "+f"(d[3])
        : "r"(a[0]), "r"(a[1]), "r"(a[2]), "r"(a[3]), "r"(b[0]), "r"(b[1]));
}

#define LDSM4(r_, a_)                                                         \
    asm volatile("ldmatrix.sync.aligned.m8n8.x4.shared.b16 {%0,%1,%2,%3}, [%4];" \
                 : "=r"((r_)[0]), "=r"((r_)[1]), "=r"((r_)[2]), "=r"((r_)[3])  \
                 : "r"(a_))

__device__ __forceinline__ uint32_t sp(const void* p) {
    return (uint32_t)__cvta_generic_to_shared(p);
}

__device__ __forceinline__ void split2f(float v0, float v1, uint32_t& hw,
                                        uint32_t& lw) {
    asm("cvt.rn.bf16x2.f32 %0, %1, %2;" : "=r"(hw) : "f"(v1), "f"(v0));
    float h0 = __uint_as_float(hw << 16);
    float h1 = __uint_as_float(hw & 0xffff0000u);
    float l0 = v0 - h0, l1 = v1 - h1;
    asm("cvt.rn.bf16x2.f32 %0, %1, %2;" : "=r"(lw) : "f"(l1), "f"(l0));
}

__device__ __forceinline__ void zero4(float a[4][4]) {
#pragma unroll
    for (int i = 0; i < 4; i++)
#pragma unroll
        for (int j = 0; j < 4; j++) a[i][j] = 0.f;
}

// ldmatrix octet addressing
__device__ __forceinline__ uint32_t a_off(int r0, int lane) {
    return (uint32_t)((r0 + (lane & 7) + ((lane >> 3) & 1) * 8) * PITCHB +
                      (lane >> 4) * 16);
}
__device__ __forceinline__ uint32_t b_off(int c0, int lane) {
    return (uint32_t)((c0 + (lane & 7) + (lane >> 4) * 8) * PITCHB +
                      ((lane >> 3) & 1) * 16);
}

// Single product acc += Ph@Qh + Ph@Ql + Pl@Qh; m16 rows r0, n32 cols c0.
// Double-buffered fragments: k+1 LDSMs issue before k's MMAs.
__device__ __forceinline__ void mm_half(const uint32_t* Ph, const uint32_t* Pl,
                                        const uint32_t* Qh, const uint32_t* Ql,
                                        float acc[4][4], int r0, int c0,
                                        int lane) {
    const uint32_t ao = a_off(r0, lane), bo = b_off(c0, lane);
    uint32_t pah = sp(Ph) + ao, pal = sp(Pl) + ao;
    uint32_t qh0 = sp(Qh) + bo, qh1 = qh0 + 16 * PITCHB;
    uint32_t ql0 = sp(Ql) + bo, ql1 = ql0 + 16 * PITCHB;
    uint32_t ah[2][4], al[2][4], bh[2][8], bl[2][8];
    LDSM4(ah[0], pah); LDSM4(al[0], pal);
    LDSM4(bh[0], qh0); LDSM4(bh[0] + 4, qh1);
    LDSM4(bl[0], ql0); LDSM4(bl[0] + 4, ql1);
#pragma unroll
    for (int k = 0; k < 8; k++) {
        const int c = k & 1, n = c ^ 1;
        if (k < 7) {
            pah += 32; pal += 32; qh0 += 32; qh1 += 32; ql0 += 32; ql1 += 32;
            LDSM4(ah[n], pah); LDSM4(al[n], pal);
            LDSM4(bh[n], qh0); LDSM4(bh[n] + 4, qh1);
            LDSM4(bl[n], ql0); LDSM4(bl[n] + 4, ql1);
        }
#pragma unroll
        for (int ni = 0; ni < 4; ni++) {
            mma16816(acc[ni], ah[c], bh[c] + ni * 2);
            mma16816(acc[ni], ah[c], bl[c] + ni * 2);
            mma16816(acc[ni], al[c], bh[c] + ni * 2);
        }
    }
}

// Paired products sharing B: accY += Y@T, accZ += Z@T. Double-buffered.
__device__ __forceinline__ void mm_pair(const uint32_t* Yh, const uint32_t* Yl,
                                        const uint32_t* Zh, const uint32_t* Zl,
                                        const uint32_t* Th, const uint32_t* Tl,
                                        float accY[4][4], float accZ[4][4],
                                        int r0, int c0, int lane) {
    const uint32_t ao = a_off(r0, lane), bo = b_off(c0, lane);
    uint32_t pyh = sp(Yh) + ao, pyl = sp(Yl) + ao;
    uint32_t pzh = sp(Zh) + ao, pzl = sp(Zl) + ao;
    uint32_t qh0 = sp(Th) + bo, qh1 = qh0 + 16 * PITCHB;
    uint32_t ql0 = sp(Tl) + bo, ql1 = ql0 + 16 * PITCHB;
    uint32_t ayh[2][4], ayl[2][4], azh[2][4], azl[2][4], bh[2][8], bl[2][8];
    LDSM4(ayh[0], pyh); LDSM4(ayl[0], pyl);
    LDSM4(azh[0], pzh); LDSM4(azl[0], pzl);
    LDSM4(bh[0], qh0); LDSM4(bh[0] + 4, qh1);
    LDSM4(bl[0], ql0); LDSM4(bl[0] + 4, ql1);
#pragma unroll
    for (int k = 0; k < 8; k++) {
        const int c = k & 1, n = c ^ 1;
        if (k < 7) {
            pyh += 32; pyl += 32; pzh += 32; pzl += 32;
            qh0 += 32; qh1 += 32; ql0 += 32; ql1 += 32;
            LDSM4(ayh[n], pyh); LDSM4(ayl[n], pyl);
            LDSM4(azh[n], pzh); LDSM4(azl[n], pzl);
            LDSM4(bh[n], qh0); LDSM4(bh[n] + 4, qh1);
            LDSM4(bl[n], ql0); LDSM4(bl[n] + 4, ql1);
        }
#pragma unroll
        for (int ni = 0; ni < 4; ni++) {
            mma16816(accY[ni], ayh[c], bh[c] + ni * 2);
            mma16816(accY[ni], ayh[c], bl[c] + ni * 2);
            mma16816(accY[ni], ayl[c], bh[c] + ni * 2);
            mma16816(accZ[ni], azh[c], bh[c] + ni * 2);
            mma16816(accZ[ni], azh[c], bl[c] + ni * 2);
            mma16816(accZ[ni], azl[c], bh[c] + ni * 2);
        }
    }
}

// v = alpha*acc + beta*I -> hi/lo pair; optional mirror to transposed pos.
__device__ __forceinline__ void epi_half(const float acc[4][4],
                                         uint32_t* __restrict__ Bh,
                                         uint32_t* __restrict__ Bl, float alpha,
                                         float beta, int r0, int c0, int lane,
                                         bool mir) {
    const int qr = lane >> 2, cp = (lane & 3) * 2;
    uint16_t* H16 = (uint16_t*)Bh;
    uint16_t* L16 = (uint16_t*)Bl;
#pragma unroll
    for (int ni = 0; ni < 4; ni++) {
        const int col = c0 + ni * 8 + cp;
#pragma unroll
        for (int h = 0; h < 2; h++) {
            const int row = r0 + qr + h * 8;
            float v0 = alpha * acc[ni][2 * h]     + ((row == col)     ? beta : 0.f);
            float v1 = alpha * acc[ni][2 * h + 1] + ((row == col + 1) ? beta : 0.f);
            uint32_t hw, lw;
            split2f(v0, v1, hw, lw);
            const int idx = row * PITCH32 + (col >> 1);
            Bh[idx] = hw;
            Bl[idx] = lw;
            if (mir) {
                H16[col * PITCH16 + row]       = (uint16_t)hw;
                H16[(col + 1) * PITCH16 + row] = (uint16_t)(hw >> 16);
                L16[col * PITCH16 + row]       = (uint16_t)lw;
                L16[(col + 1) * PITCH16 + row] = (uint16_t)(lw >> 16);
            }
        }
    }
}

__device__ __forceinline__ void epi_out_half(const float acc[4][4],
                                             float* __restrict__ Ob, float s,
                                             int r0, int c0, int lane) {
    const int qr = lane >> 2, cp = (lane & 3) * 2;
#pragma unroll
    for (int ni = 0; ni < 4; ni++) {
        const int col = c0 + ni * 8 + cp;
#pragma unroll
        for (int h = 0; h < 2; h++) {
            const int row = r0 + qr + h * 8;
            *(float2*)(Ob + row * 128 + col) =
                make_float2(s * acc[ni][2 * h], s * acc[ni][2 * h + 1]);
        }
    }
}

__device__ __constant__ int LTI[10] = {0, 1, 1, 2, 2, 2, 3, 3, 3, 3};
__device__ __constant__ int LTJ[10] = {0, 0, 1, 0, 1, 2, 0, 1, 2, 3};

__global__ void __launch_bounds__(NT, 1)
ns_pipe_kernel(const float* __restrict__ A, float* __restrict__ Out) {
    extern __shared__ uint32_t sm[];
    uint32_t* Yh = sm;
    uint32_t* Yl = sm + 128 * PITCH32;
    uint32_t* Zh = sm + 2 * 128 * PITCH32;
    uint32_t* Zl = sm + 3 * 128 * PITCH32;
    uint32_t* Th = sm + 4 * 128 * PITCH32;
    uint32_t* Tl = sm + 5 * 128 * PITCH32;
    __shared__ float red[12];

    const int tid = threadIdx.x, w = tid >> 5, lane = tid & 31;
    const float* Ab = A + (size_t)blockIdx.x * 16384;
    float* Ob = Out + (size_t)blockIdx.x * 16384;

    // --- Task geometry (20 triangular halves; task t: p=t%10, h=t/10) ---
    // Warp w owns tasks w and w+12 (if < 20). Per-SMSP: exactly 5 tasks.
    const int t0 = w;
    const int p0 = t0 % 10, h0 = t0 / 10;
    const int T0r = LTI[p0] * 32 + h0 * 16, T0c = LTJ[p0] * 32;
    const bool T0m = (LTI[p0] != LTJ[p0]);
    const bool has1 = (w < 8);
    const int t1 = w + 12;
    const int p1 = t1 % 10, h1 = t1 / 10;
    const int T1r = LTI[p1] * 32 + h1 * 16, T1c = LTJ[p1] * 32;
    const bool T1m = (LTI[p1] != LTJ[p1]);
    // Last full grid: 32 halves; warp w owns w, w+12, (w<8) w+24.
    const int La = w,      Lar = (La & 7) * 16,  Lac = (La >> 3) * 32;
    const int Lb = w + 12, Lbr = (Lb & 7) * 16,  Lbc = (Lb >> 3) * 32;
    const int Lc = w + 24, Lcr = (Lc & 7) * 16,  Lcc = (Lc >> 3) * 32;

    // ---- Frobenius norm ----
    float ss = 0.f;
    const float4* A4 = (const float4*)Ab;
    for (int i = tid; i < 4096; i += NT) {
        float4 v = A4[i];
        ss = fmaf(v.x, v.x, fmaf(v.y, v.y, fmaf(v.z, v.z, fmaf(v.w, v.w, ss))));
    }
#pragma unroll
    for (int o = 16; o; o >>= 1) ss += __shfl_xor_sync(0xffffffffu, ss, o);
    if (lane == 0) red[w] = ss;
    __syncthreads();
    float tot = 0.f;
#pragma unroll
    for (int i = 0; i < 12; i++) tot += red[i];
    const float normA = sqrtf(tot);
    const float inv = 1.f / normA;

    // ---- Init: Y0 = A*inv; T1 = Z1 = 1.5I - 0.5*Y0 (all split) ----
    for (int u = tid; u < 2048; u += NT) {
        const int row = u >> 4;
        const int col = (u & 15) * 8;
        float4 a0 = *(const float4*)(Ab + row * 128 + col);
        float4 a1 = *(const float4*)(Ab + row * 128 + col + 4);
        float yv[8] = {a0.x * inv, a0.y * inv, a0.z * inv, a0.w * inv,
                       a1.x * inv, a1.y * inv, a1.z * inv, a1.w * inv};
#pragma unroll
        for (int jj = 0; jj < 4; jj++) {
            const int cc = col + 2 * jj;
            const int idx = row * PITCH32 + (cc >> 1);
            uint32_t hw, lw;
            split2f(yv[2 * jj], yv[2 * jj + 1], hw, lw);
            Yh[idx] = hw; Yl[idx] = lw;
            float q0 = -0.5f * yv[2 * jj]     + (row == cc     ? 1.5f : 0.f);
            float q1 = -0.5f * yv[2 * jj + 1] + (row == cc + 1 ? 1.5f : 0.f);
            split2f(q0, q1, hw, lw);
            Th[idx] = hw; Tl[idx] = lw;
            Zh[idx] = hw; Zl[idx] = lw;
        }
    }
    __syncthreads();

    // ---- iter 1 (reduced): Y = Y @ T1, triangular ----
    {
        float a0[4][4], a1[4][4];
        zero4(a0);
        mm_half(Yh, Yl, Th, Tl, a0, T0r, T0c, lane);
        if (has1) {
            zero4(a1);
            mm_half(Yh, Yl, Th, Tl, a1, T1r, T1c, lane);
        }
        __syncthreads();
        epi_half(a0, Yh, Yl, 1.f, 0.f, T0r, T0c, lane, T0m);
        if (has1) epi_half(a1, Yh, Yl, 1.f, 0.f, T1r, T1c, lane, T1m);
        __syncthreads();
    }

    // ---- iters 2..5 ----
#pragma unroll 1
    for (int it = 1; it < 5; ++it) {
        // P1: T = 1.5I - 0.5*(Z @ Y); epilogue fused (T not a P1 operand)
        {
            float a0[4][4];
            zero4(a0);
            mm_half(Zh, Zl, Yh, Yl, a0, T0r, T0c, lane);
            epi_half(a0, Th, Tl, -0.5f, 1.5f, T0r, T0c, lane, T0m);
            if (has1) {
                zero4(a0);
                mm_half(Zh, Zl, Yh, Yl, a0, T1r, T1c, lane);
                epi_half(a0, Th, Tl, -0.5f, 1.5f, T1r, T1c, lane, T1m);
            }
        }
        __syncthreads();

        if (it < 4) {
            // P2: Y = Y@T and Z = Z@T as paired tasks (shared B fragments)
            float ay0[4][4], az0[4][4];
            zero4(ay0); zero4(az0);
            mm_pair(Yh, Yl, Zh, Zl, Th, Tl, ay0, az0, T0r, T0c, lane);
            float ay1[4][4], az1[4][4];
            if (has1) {
                zero4(ay1); zero4(az1);
                mm_pair(Yh, Yl, Zh, Zl, Th, Tl, ay1, az1, T1r, T1c, lane);
            }
            __syncthreads();
            epi_half(ay0, Yh, Yl, 1.f, 0.f, T0r, T0c, lane, T0m);
            epi_half(az0, Zh, Zl, 1.f, 0.f, T0r, T0c, lane, T0m);
            if (has1) {
                epi_half(ay1, Yh, Yl, 1.f, 0.f, T1r, T1c, lane, T1m);
                epi_half(az1, Zh, Zl, 1.f, 0.f, T1r, T1c, lane, T1m);
            }
            __syncthreads();
        } else {
            // Last: Y5 = Y@T full grid, straight to GMEM
            const float s = sqrtf(normA);
            float a0[4][4];
            zero4(a0);
            mm_half(Yh, Yl, Th, Tl, a0, Lar, Lac, lane);
            epi_out_half(a0, Ob, s, Lar, Lac, lane);
            zero4(a0);
            mm_half(Yh, Yl, Th, Tl, a0, Lbr, Lbc, lane);
            epi_out_half(a0, Ob, s, Lbr, Lbc, lane);
            if (w < 8) {
                zero4(a0);
                mm_half(Yh, Yl, Th, Tl, a0, Lcr, Lcc, lane);
                epi_out_half(a0, Ob, s, Lcr, Lcc, lane);
            }
        }
    }
}

extern "C" void kernel_launch(void* const* d_in, const int* in_sizes, int n_in,
                              void* d_out, int out_size) {
    const float* A = (const float*)d_in[0];
    float* out = (float*)d_out;
    const int nbatch = in_sizes[0] / (NMAT * NMAT);            // 1024
    const size_t smem = 6 * 128 * PITCH32 * sizeof(uint32_t);  // 208896 B
    cudaFuncSetAttribute(ns_pipe_kernel,
                         cudaFuncAttributeMaxDynamicSharedMemorySize, (int)smem);
    ns_pipe_kernel<<<nbatch, NT, smem>>>(A, out);
}